// round 1
// baseline (speedup 1.0000x reference)
#include <cuda_runtime.h>
#include <cuda_bf16.h>

// ---------------- problem constants ----------------
#define BATCH 2
#define DIM 32              // D = H = W = 32
#define CC 384              // channels
#define NHEAD 12
#define HD 32               // head dim
#define NTOK 64             // tokens per window (4*4*4)
#define NWIN 1024           // B * (32/4)^3
#define TOK 65536           // total tokens = NWIN * NTOK
#define HMLP 1536
#define QSCALE 0.17677669529663687f   // 32^-0.5

// ---------------- scratch (device globals; no allocations) ----------------
__device__ float g_xw [TOK * CC];   // LN1 + shift + window-partitioned tokens
__device__ float g_q  [TOK * CC];   // [win][head][n][d]
__device__ float g_k  [TOK * CC];
__device__ float g_v  [TOK * CC];
__device__ float g_ao [TOK * CC];   // attention output, window-token order
__device__ float g_x2 [TOK * CC];   // residual after attention, natural order
__device__ float g_ln2[TOK * CC];   // LN2 output, natural order
__device__ float g_mlp[TOK * HMLP]; // MLP hidden

// ---------------- LayerNorm kernels ----------------
// MODE 0: read x at shifted/partitioned source coord, LN, write g_xw (window order)
// MODE 1: read g_x2 (natural), LN, write g_ln2
template<int MODE>
__global__ __launch_bounds__(128) void ln_kernel(const float* __restrict__ xin,
                                                 const float* __restrict__ gamma,
                                                 const float* __restrict__ beta)
{
    int t = blockIdx.x;
    const float* src;
    float* dst;
    if constexpr (MODE == 0) {
        int g = t >> 6, n = t & 63;
        int b = g >> 9, wd = (g >> 6) & 7, wh = (g >> 3) & 7, ww = g & 7;
        int i = n >> 4, j = (n >> 2) & 3, k = n & 3;
        int d0 = (wd * 4 + i + 2) & 31;
        int h0 = (wh * 4 + j + 2) & 31;
        int w0 = (ww * 4 + k + 2) & 31;
        src = xin + (size_t)(((b * 32 + d0) * 32 + h0) * 32 + w0) * CC;
        dst = g_xw + (size_t)t * CC;
    } else {
        src = g_x2 + (size_t)t * CC;
        dst = g_ln2 + (size_t)t * CC;
    }
    int tid = threadIdx.x;
    float v0 = src[tid], v1 = src[tid + 128], v2 = src[tid + 256];
    float s = v0 + v1 + v2;
    float ss = v0 * v0 + v1 * v1 + v2 * v2;
    #pragma unroll
    for (int o = 16; o > 0; o >>= 1) {
        s  += __shfl_xor_sync(0xffffffffu, s, o);
        ss += __shfl_xor_sync(0xffffffffu, ss, o);
    }
    __shared__ float red[8];
    if ((tid & 31) == 0) { red[tid >> 5] = s; red[4 + (tid >> 5)] = ss; }
    __syncthreads();
    s  = red[0] + red[1] + red[2] + red[3];
    ss = red[4] + red[5] + red[6] + red[7];
    float mu  = s * (1.0f / CC);
    float var = ss * (1.0f / CC) - mu * mu;
    float inv = rsqrtf(var + 1e-5f);
    dst[tid]       = (v0 - mu) * inv * gamma[tid]       + beta[tid];
    dst[tid + 128] = (v1 - mu) * inv * gamma[tid + 128] + beta[tid + 128];
    dst[tid + 256] = (v2 - mu) * inv * gamma[tid + 256] + beta[tid + 256];
}

// ---------------- tiled fp32 GEMM: Y = A @ Bw^T + bias, fused epilogues -----
// A: [M,K] row-major (selected from device globals by EPI)
// Bw: [N,K] row-major (weight as stored: [out_features, in_features])
// EPI 0: QKV   -> scatter to g_q/g_k/g_v (q scaled)
// EPI 1: PROJ  -> un-partition + un-shift + residual(x) -> g_x2
// EPI 2: MLP1  -> exact GELU -> g_mlp
// EPI 3: MLP2  -> + residual(g_x2) -> d_out
template<int EPI, int N, int K>
__global__ __launch_bounds__(256) void sgemm(const float* __restrict__ Bw,
                                             const float* __restrict__ bias,
                                             float* __restrict__ Cout,
                                             const float* __restrict__ extra)
{
    const float* A;
    if constexpr (EPI == 0)      A = g_xw;
    else if constexpr (EPI == 1) A = g_ao;
    else if constexpr (EPI == 2) A = g_ln2;
    else                         A = g_mlp;

    __shared__ float As[16][68];
    __shared__ float Bs[16][68];

    int m0 = blockIdx.y * 64;
    int n0 = blockIdx.x * 64;
    int tid = threadIdx.x;
    int tx = tid & 15, ty = tid >> 4;
    int lr = tid >> 2;          // 0..63 (tile row)
    int lc = (tid & 3) * 4;     // 0,4,8,12 (k within tile)

    const float* Ap = A  + (size_t)(m0 + lr) * K + lc;
    const float* Bp = Bw + (size_t)(n0 + lr) * K + lc;

    float acc[4][4] = {};
    for (int k0 = 0; k0 < K; k0 += 16) {
        float4 a = *(const float4*)(Ap + k0);
        float4 b = *(const float4*)(Bp + k0);
        As[lc + 0][lr] = a.x; As[lc + 1][lr] = a.y;
        As[lc + 2][lr] = a.z; As[lc + 3][lr] = a.w;
        Bs[lc + 0][lr] = b.x; Bs[lc + 1][lr] = b.y;
        Bs[lc + 2][lr] = b.z; Bs[lc + 3][lr] = b.w;
        __syncthreads();
        #pragma unroll
        for (int kk = 0; kk < 16; kk++) {
            float av[4], bv[4];
            #pragma unroll
            for (int u = 0; u < 4; u++) { av[u] = As[kk][ty * 4 + u]; bv[u] = Bs[kk][tx * 4 + u]; }
            #pragma unroll
            for (int u = 0; u < 4; u++)
                #pragma unroll
                for (int v = 0; v < 4; v++) acc[u][v] += av[u] * bv[v];
        }
        __syncthreads();
    }

    #pragma unroll
    for (int u = 0; u < 4; u++) {
        int m = m0 + ty * 4 + u;
        #pragma unroll
        for (int v = 0; v < 4; v++) {
            int n = n0 + tx * 4 + v;
            float val = acc[u][v] + bias[n];
            if constexpr (EPI == 0) {
                int s = n / CC; int r = n - s * CC; int h = r >> 5; int d = r & 31;
                int g = m >> 6; int nn = m & 63;
                float* dst;
                if (s == 0)      { val *= QSCALE; dst = g_q; }
                else if (s == 1) dst = g_k;
                else             dst = g_v;
                dst[(((g * NHEAD + h) * NTOK) + nn) * HD + d] = val;
            } else if constexpr (EPI == 1) {
                int g = m >> 6; int nn = m & 63;
                int b = g >> 9, wd = (g >> 6) & 7, wh = (g >> 3) & 7, ww = g & 7;
                int i = nn >> 4, j = (nn >> 2) & 3, kkk = nn & 3;
                int d0 = (wd * 4 + i + 2) & 31;
                int h0 = (wh * 4 + j + 2) & 31;
                int w0 = (ww * 4 + kkk + 2) & 31;
                size_t nat = (size_t)(((b * 32 + d0) * 32 + h0) * 32 + w0) * CC + n;
                g_x2[nat] = val + extra[nat];
            } else if constexpr (EPI == 2) {
                g_mlp[(size_t)m * HMLP + n] = val * 0.5f * (1.0f + erff(val * 0.70710678118654752f));
            } else {
                size_t o = (size_t)m * CC + n;
                Cout[o] = val + g_x2[o];
            }
        }
    }
}

// ---------------- windowed attention: one block per (window, head) ---------
__global__ __launch_bounds__(64) void attn_kernel(const float* __restrict__ bias_table)
{
    int g = blockIdx.x;     // window 0..1023
    int h = blockIdx.y;     // head 0..11
    __shared__ float sq[64][33];
    __shared__ float sk[64][33];
    __shared__ float sv[64][33];
    __shared__ float sbias[343];

    int tid = threadIdx.x;
    const float* qb = g_q + (size_t)(g * NHEAD + h) * NTOK * HD;
    const float* kb = g_k + (size_t)(g * NHEAD + h) * NTOK * HD;
    const float* vb = g_v + (size_t)(g * NHEAD + h) * NTOK * HD;
    for (int idx = tid; idx < NTOK * HD; idx += 64) {
        sq[idx >> 5][idx & 31] = qb[idx];
        sk[idx >> 5][idx & 31] = kb[idx];
        sv[idx >> 5][idx & 31] = vb[idx];
    }
    for (int idx = tid; idx < 343; idx += 64) sbias[idx] = bias_table[idx * NHEAD + h];
    __syncthreads();

    int n = tid;
    int i = n >> 4, j = (n >> 2) & 3, kk = n & 3;
    int wd = (g >> 6) & 7, wh = (g >> 3) & 7, ww = g & 7;
    // shift-mask region id for this query (region r(c): c<28 ->0, c<30 ->1, else 2)
    int rd = (wd < 7) ? 0 : ((i  < 2) ? 1 : 2);
    int rh = (wh < 7) ? 0 : ((j  < 2) ? 1 : 2);
    int rw = (ww < 7) ? 0 : ((kk < 2) ? 1 : 2);
    int cn = rd * 9 + rh * 3 + rw;

    float qv[32];
    #pragma unroll
    for (int d = 0; d < 32; d++) qv[d] = sq[n][d];

    float s[64];
    float mx = -1e30f;
    #pragma unroll 4
    for (int m = 0; m < 64; m++) {
        float acc = 0.f;
        #pragma unroll
        for (int d = 0; d < 32; d++) acc += qv[d] * sk[m][d];
        int i2 = m >> 4, j2 = (m >> 2) & 3, k2 = m & 3;
        int idx = (i - i2 + 3) * 49 + (j - j2 + 3) * 7 + (kk - k2 + 3);
        acc += sbias[idx];
        int cm = ((wd < 7) ? 0 : ((i2 < 2) ? 1 : 2)) * 9
               + ((wh < 7) ? 0 : ((j2 < 2) ? 1 : 2)) * 3
               + ((ww < 7) ? 0 : ((k2 < 2) ? 1 : 2));
        if (cm != cn) acc -= 100.0f;
        s[m] = acc;
        mx = fmaxf(mx, acc);
    }
    float sum = 0.f;
    #pragma unroll
    for (int m = 0; m < 64; m++) { s[m] = __expf(s[m] - mx); sum += s[m]; }
    float r = 1.0f / sum;

    float o[32];
    #pragma unroll
    for (int d = 0; d < 32; d++) o[d] = 0.f;
    #pragma unroll 4
    for (int m = 0; m < 64; m++) {
        float p = s[m] * r;
        #pragma unroll
        for (int d = 0; d < 32; d++) o[d] += p * sv[m][d];
    }
    float* dst = g_ao + (size_t)(g * NTOK + n) * CC + h * HD;
    #pragma unroll
    for (int d = 0; d < 32; d++) dst[d] = o[d];
}

// ---------------- launch ----------------
extern "C" void kernel_launch(void* const* d_in, const int* in_sizes, int n_in,
                              void* d_out, int out_size)
{
    const float* x          = (const float*)d_in[0];
    const float* g1         = (const float*)d_in[1];
    const float* b1         = (const float*)d_in[2];
    const float* Wqkv       = (const float*)d_in[3];
    const float* bqkv       = (const float*)d_in[4];
    const float* bias_table = (const float*)d_in[5];
    const float* Wp         = (const float*)d_in[6];
    const float* bp         = (const float*)d_in[7];
    const float* g2         = (const float*)d_in[8];
    const float* b2         = (const float*)d_in[9];
    const float* W1         = (const float*)d_in[10];
    const float* bb1        = (const float*)d_in[11];
    const float* W2         = (const float*)d_in[12];
    const float* bb2        = (const float*)d_in[13];
    float* out = (float*)d_out;

    ln_kernel<0><<<TOK, 128>>>(x, g1, b1);
    sgemm<0, 3 * CC, CC><<<dim3((3 * CC) / 64, TOK / 64), 256>>>(Wqkv, bqkv, nullptr, nullptr);
    attn_kernel<<<dim3(NWIN, NHEAD), 64>>>(bias_table);
    sgemm<1, CC, CC><<<dim3(CC / 64, TOK / 64), 256>>>(Wp, bp, nullptr, x);
    ln_kernel<1><<<TOK, 128>>>(nullptr, g2, b2);
    sgemm<2, HMLP, CC><<<dim3(HMLP / 64, TOK / 64), 256>>>(W1, bb1, nullptr, nullptr);
    sgemm<3, CC, HMLP><<<dim3(CC / 64, TOK / 64), 256>>>(W2, bb2, out, nullptr);
}

// round 3
// speedup vs baseline: 2.0567x; 2.0567x over previous
#include <cuda_runtime.h>
#include <cuda_bf16.h>
#include <cstdint>

// ---------------- problem constants ----------------
#define CC 384
#define NHEAD 12
#define HD 32
#define NTOK 64
#define NWIN 1024
#define TOK 65536
#define HMLP 1536
#define QSCALE 0.17677669529663687f   // 32^-0.5

// ---------------- scratch (device globals; no allocations) ----------------
__device__ __nv_bfloat16 g_xw_h [TOK * CC],  g_xw_l [TOK * CC];
__device__ __nv_bfloat16 g_ao_h [TOK * CC],  g_ao_l [TOK * CC];
__device__ __nv_bfloat16 g_ln2_h[TOK * CC],  g_ln2_l[TOK * CC];
__device__ __nv_bfloat16 g_mlp_h[TOK * HMLP],g_mlp_l[TOK * HMLP];
__device__ __nv_bfloat16 g_wqkv_h[3*CC*CC],  g_wqkv_l[3*CC*CC];
__device__ __nv_bfloat16 g_wp_h [CC*CC],     g_wp_l [CC*CC];
__device__ __nv_bfloat16 g_w1_h [HMLP*CC],   g_w1_l [HMLP*CC];
__device__ __nv_bfloat16 g_w2_h [CC*HMLP],   g_w2_l [CC*HMLP];
__device__ float g_q [TOK * CC];
__device__ float g_k [TOK * CC];
__device__ float g_v [TOK * CC];
__device__ float g_x2[TOK * CC];

// ---------------- helpers ----------------
__device__ __forceinline__ uint32_t smem_u32(const void* p) {
    uint32_t a;
    asm("{ .reg .u64 t; cvta.to.shared.u64 t, %1; cvt.u32.u64 %0, t; }" : "=r"(a) : "l"(p));
    return a;
}
__device__ __forceinline__ void cp16(uint32_t saddr, const void* gaddr) {
    asm volatile("cp.async.cg.shared.global [%0], [%1], 16;" :: "r"(saddr), "l"(gaddr));
}
__device__ __forceinline__ void cp_commit() {
    asm volatile("cp.async.commit_group;");
}
__device__ __forceinline__ void ldm4(uint32_t* r, uint32_t addr) {
    asm volatile("ldmatrix.sync.aligned.m8n8.x4.shared.b16 {%0,%1,%2,%3}, [%4];"
                 : "=r"(r[0]), "=r"(r[1]), "=r"(r[2]), "=r"(r[3]) : "r"(addr));
}
__device__ __forceinline__ void mma16816(float* c, const uint32_t* a, const uint32_t* b) {
    asm volatile("mma.sync.aligned.m16n8k16.row.col.f32.bf16.bf16.f32 "
                 "{%0,%1,%2,%3}, {%4,%5,%6,%7}, {%8,%9}, {%0,%1,%2,%3};"
                 : "+f"(c[0]), "+f"(c[1]), "+f"(c[2]), "+f"(c[3])
                 : "r"(a[0]), "r"(a[1]), "r"(a[2]), "r"(a[3]), "r"(b[0]), "r"(b[1]));
}
__device__ __forceinline__ void split_bf16(float v, __nv_bfloat16& h, __nv_bfloat16& l) {
    h = __float2bfloat16(v);
    l = __float2bfloat16(v - __bfloat162float(h));
}

// ---------------- weight fp32 -> bf16 hi/lo ----------------
__global__ void cvt_kernel(const float* __restrict__ w, __nv_bfloat16* __restrict__ h,
                           __nv_bfloat16* __restrict__ l, int n) {
    int i = blockIdx.x * 256 + threadIdx.x;
    if (i < n) split_bf16(w[i], h[i], l[i]);
}

// ---------------- LayerNorm ----------------
template<int MODE>
__global__ __launch_bounds__(128) void ln_kernel(const float* __restrict__ xin,
                                                 const float* __restrict__ gamma,
                                                 const float* __restrict__ beta)
{
    int t = blockIdx.x;
    const float* src;
    __nv_bfloat16 *dh, *dl;
    if constexpr (MODE == 0) {
        int g = t >> 6, n = t & 63;
        int b = g >> 9, wd = (g >> 6) & 7, wh = (g >> 3) & 7, ww = g & 7;
        int i = n >> 4, j = (n >> 2) & 3, k = n & 3;
        int d0 = (wd * 4 + i + 2) & 31;
        int h0 = (wh * 4 + j + 2) & 31;
        int w0 = (ww * 4 + k + 2) & 31;
        src = xin + (size_t)(((b * 32 + d0) * 32 + h0) * 32 + w0) * CC;
        dh = g_xw_h + (size_t)t * CC; dl = g_xw_l + (size_t)t * CC;
    } else {
        src = g_x2 + (size_t)t * CC;
        dh = g_ln2_h + (size_t)t * CC; dl = g_ln2_l + (size_t)t * CC;
    }
    int tid = threadIdx.x;
    float v0 = src[tid], v1 = src[tid + 128], v2 = src[tid + 256];
    float s = v0 + v1 + v2;
    float ss = v0 * v0 + v1 * v1 + v2 * v2;
    #pragma unroll
    for (int o = 16; o > 0; o >>= 1) {
        s  += __shfl_xor_sync(0xffffffffu, s, o);
        ss += __shfl_xor_sync(0xffffffffu, ss, o);
    }
    __shared__ float red[8];
    if ((tid & 31) == 0) { red[tid >> 5] = s; red[4 + (tid >> 5)] = ss; }
    __syncthreads();
    s  = red[0] + red[1] + red[2] + red[3];
    ss = red[4] + red[5] + red[6] + red[7];
    float mu  = s * (1.0f / CC);
    float var = ss * (1.0f / CC) - mu * mu;
    float inv = rsqrtf(var + 1e-5f);
    float o0 = (v0 - mu) * inv * gamma[tid]       + beta[tid];
    float o1 = (v1 - mu) * inv * gamma[tid + 128] + beta[tid + 128];
    float o2 = (v2 - mu) * inv * gamma[tid + 256] + beta[tid + 256];
    split_bf16(o0, dh[tid],       dl[tid]);
    split_bf16(o1, dh[tid + 128], dl[tid + 128]);
    split_bf16(o2, dh[tid + 256], dl[tid + 256]);
}

// ---------------- mma.sync split-bf16 GEMM: C = A @ Bw^T + bias ------------
// 128x128 CTA tile, BK=32, double-buffered cp.async. 8 warps -> 64x32 each.
// 3-term split product (Ah*Bh + Ah*Bl + Al*Bh) into fp32 accumulators.
// EPI 0: QKV scatter   EPI 1: proj+unshift+residual   EPI 2: GELU   EPI 3: +res -> out
#define STG_A_H 0
#define STG_A_L 10240
#define STG_B_H 20480
#define STG_B_L 30720
#define STG_SZ  40960

template<int EPI, int N, int K>
__global__ __launch_bounds__(256, 1) void tgemm(const float* __restrict__ bias,
                                                float* __restrict__ Cout,
                                                const float* __restrict__ extra)
{
    const __nv_bfloat16 *Ah, *Al, *Bh, *Bl;
    if constexpr (EPI == 0)      { Ah = g_xw_h;  Al = g_xw_l;  Bh = g_wqkv_h; Bl = g_wqkv_l; }
    else if constexpr (EPI == 1) { Ah = g_ao_h;  Al = g_ao_l;  Bh = g_wp_h;   Bl = g_wp_l;   }
    else if constexpr (EPI == 2) { Ah = g_ln2_h; Al = g_ln2_l; Bh = g_w1_h;   Bl = g_w1_l;   }
    else                         { Ah = g_mlp_h; Al = g_mlp_l; Bh = g_w2_h;   Bl = g_w2_l;   }

    extern __shared__ char smem[];
    const uint32_t sb = smem_u32(smem);
    const int tid = threadIdx.x;
    const int wid = tid >> 5, lane = tid & 31;
    const int wm = wid & 1, wn = wid >> 1;          // warp -> 64m x 32n
    const int m0 = blockIdx.y * 128, n0 = blockIdx.x * 128;
    constexpr int NC = K / 32;

    // global -> smem (cp.async), one 128x32 bf16 tile per matrix, rows padded to 40 elems
    auto issue = [&](int c, int st) {
        int k0 = c * 32;
        uint32_t base = sb + (uint32_t)st * STG_SZ;
        #pragma unroll
        for (int t = 0; t < 2; t++) {
            int e = tid + t * 256;
            int r = e >> 2, cv = e & 3;
            uint32_t so = (uint32_t)(r * 80 + cv * 16);
            size_t ga = (size_t)(m0 + r) * K + k0 + cv * 8;
            size_t gb = (size_t)(n0 + r) * K + k0 + cv * 8;
            cp16(base + STG_A_H + so, Ah + ga);
            cp16(base + STG_A_L + so, Al + ga);
            cp16(base + STG_B_H + so, Bh + gb);
            cp16(base + STG_B_L + so, Bl + gb);
        }
        cp_commit();
    };

    // ldmatrix lane address components
    const int lr = lane & 7;
    const int aRow = wm * 64 + lr + ((lane >> 3) & 1) * 8;   // + mt*16
    const int aK   = (lane >> 4) * 8;                        // + ks*16
    const int bRow = wn * 32 + lr + (lane >> 4) * 8;         // + p*16
    const int bK   = ((lane >> 3) & 1) * 8;                  // + ks*16

    float acc[4][4][4];
    #pragma unroll
    for (int a = 0; a < 4; a++)
        #pragma unroll
        for (int b = 0; b < 4; b++)
            #pragma unroll
            for (int c = 0; c < 4; c++) acc[a][b][c] = 0.f;

    issue(0, 0);

    for (int c = 0; c < NC; c++) {
        int st = c & 1;
        if (c + 1 < NC) {
            issue(c + 1, st ^ 1);
            asm volatile("cp.async.wait_group 1;");
        } else {
            asm volatile("cp.async.wait_group 0;");
        }
        __syncthreads();

        uint32_t base = sb + (uint32_t)st * STG_SZ;
        #pragma unroll
        for (int ks = 0; ks < 2; ks++) {
            uint32_t a_h[4][4], a_l[4][4];
            #pragma unroll
            for (int mt = 0; mt < 4; mt++) {
                uint32_t off = (uint32_t)((aRow + mt * 16) * 40 + ks * 16 + aK) * 2;
                ldm4(a_h[mt], base + STG_A_H + off);
                ldm4(a_l[mt], base + STG_A_L + off);
            }
            uint32_t b_h[4][2], b_l[4][2];
            #pragma unroll
            for (int p = 0; p < 2; p++) {
                uint32_t off = (uint32_t)((bRow + p * 16) * 40 + ks * 16 + bK) * 2;
                uint32_t r4[4];
                ldm4(r4, base + STG_B_H + off);
                b_h[2*p][0] = r4[0]; b_h[2*p][1] = r4[1];
                b_h[2*p+1][0] = r4[2]; b_h[2*p+1][1] = r4[3];
                ldm4(r4, base + STG_B_L + off);
                b_l[2*p][0] = r4[0]; b_l[2*p][1] = r4[1];
                b_l[2*p+1][0] = r4[2]; b_l[2*p+1][1] = r4[3];
            }
            #pragma unroll
            for (int mt = 0; mt < 4; mt++)
                #pragma unroll
                for (int nt = 0; nt < 4; nt++) {
                    mma16816(acc[mt][nt], a_h[mt], b_h[nt]);
                    mma16816(acc[mt][nt], a_h[mt], b_l[nt]);
                    mma16816(acc[mt][nt], a_l[mt], b_h[nt]);
                }
        }
        __syncthreads();
    }

    // ---------------- epilogue ----------------
    const int mrow0 = m0 + wm * 64 + (lane >> 2);
    const int ncol0 = n0 + wn * 32 + (lane & 3) * 2;

    #pragma unroll
    for (int mt = 0; mt < 4; mt++) {
        #pragma unroll
        for (int nt = 0; nt < 4; nt++) {
            #pragma unroll
            for (int half = 0; half < 2; half++) {
                int row = mrow0 + mt * 16 + half * 8;
                int col = ncol0 + nt * 8;
                float v0 = acc[mt][nt][half * 2]     + bias[col];
                float v1 = acc[mt][nt][half * 2 + 1] + bias[col + 1];

                if constexpr (EPI == 0) {
                    int s = col / CC; int rr = col - s * CC;
                    int hh = rr >> 5, d = rr & 31;
                    float* dst = (s == 0) ? g_q : (s == 1) ? g_k : g_v;
                    if (s == 0) { v0 *= QSCALE; v1 *= QSCALE; }
                    size_t o = (((size_t)(row >> 6) * NHEAD + hh) * NTOK + (row & 63)) * HD + d;
                    *(float2*)(dst + o) = make_float2(v0, v1);
                } else if constexpr (EPI == 1) {
                    int g = row >> 6, nn = row & 63;
                    int b = g >> 9, wd = (g >> 6) & 7, wh = (g >> 3) & 7, ww = g & 7;
                    int i3 = nn >> 4, j3 = (nn >> 2) & 3, k3 = nn & 3;
                    int d0 = (wd * 4 + i3 + 2) & 31;
                    int h0 = (wh * 4 + j3 + 2) & 31;
                    int w0 = (ww * 4 + k3 + 2) & 31;
                    size_t nat = (size_t)(((b * 32 + d0) * 32 + h0) * 32 + w0) * CC + col;
                    float2 e = *(const float2*)(extra + nat);
                    *(float2*)(g_x2 + nat) = make_float2(v0 + e.x, v1 + e.y);
                } else if constexpr (EPI == 2) {
                    size_t o = (size_t)row * HMLP + col;
                    float t0 = v0 * 0.5f * (1.0f + erff(v0 * 0.70710678118654752f));
                    float t1 = v1 * 0.5f * (1.0f + erff(v1 * 0.70710678118654752f));
                    __nv_bfloat16 h0b, l0b, h1b, l1b;
                    split_bf16(t0, h0b, l0b);
                    split_bf16(t1, h1b, l1b);
                    *(__nv_bfloat162*)(g_mlp_h + o) = __nv_bfloat162(h0b, h1b);
                    *(__nv_bfloat162*)(g_mlp_l + o) = __nv_bfloat162(l0b, l1b);
                } else {
                    size_t o = (size_t)row * CC + col;
                    float2 e = *(const float2*)(g_x2 + o);
                    *(float2*)(Cout + o) = make_float2(v0 + e.x, v1 + e.y);
                }
            }
        }
    }
}

// ---------------- windowed attention: one block per (window, head) ---------
__global__ __launch_bounds__(64) void attn_kernel(const float* __restrict__ bias_table)
{
    int g = blockIdx.x, h = blockIdx.y;
    __shared__ float sq[64][33];
    __shared__ float sk[64][33];
    __shared__ float sv[64][33];
    __shared__ float sbias[343];

    int tid = threadIdx.x;
    const float* qb = g_q + (size_t)(g * NHEAD + h) * NTOK * HD;
    const float* kb = g_k + (size_t)(g * NHEAD + h) * NTOK * HD;
    const float* vb = g_v + (size_t)(g * NHEAD + h) * NTOK * HD;
    for (int idx = tid; idx < NTOK * HD; idx += 64) {
        sq[idx >> 5][idx & 31] = qb[idx];
        sk[idx >> 5][idx & 31] = kb[idx];
        sv[idx >> 5][idx & 31] = vb[idx];
    }
    for (int idx = tid; idx < 343; idx += 64) sbias[idx] = bias_table[idx * NHEAD + h];
    __syncthreads();

    int n = tid;
    int i = n >> 4, j = (n >> 2) & 3, kk = n & 3;
    int wd = (g >> 6) & 7, wh = (g >> 3) & 7, ww = g & 7;
    int rd = (wd < 7) ? 0 : ((i  < 2) ? 1 : 2);
    int rh = (wh < 7) ? 0 : ((j  < 2) ? 1 : 2);
    int rw = (ww < 7) ? 0 : ((kk < 2) ? 1 : 2);
    int cn = rd * 9 + rh * 3 + rw;

    float qv[32];
    #pragma unroll
    for (int d = 0; d < 32; d++) qv[d] = sq[n][d];

    float s[64];
    float mx = -1e30f;
    #pragma unroll 4
    for (int m = 0; m < 64; m++) {
        float acc = 0.f;
        #pragma unroll
        for (int d = 0; d < 32; d++) acc += qv[d] * sk[m][d];
        int i2 = m >> 4, j2 = (m >> 2) & 3, k2 = m & 3;
        int idx = (i - i2 + 3) * 49 + (j - j2 + 3) * 7 + (kk - k2 + 3);
        acc += sbias[idx];
        int cm = ((wd < 7) ? 0 : ((i2 < 2) ? 1 : 2)) * 9
               + ((wh < 7) ? 0 : ((j2 < 2) ? 1 : 2)) * 3
               + ((ww < 7) ? 0 : ((k2 < 2) ? 1 : 2));
        if (cm != cn) acc -= 100.0f;
        s[m] = acc;
        mx = fmaxf(mx, acc);
    }
    float sum = 0.f;
    #pragma unroll
    for (int m = 0; m < 64; m++) { s[m] = __expf(s[m] - mx); sum += s[m]; }
    float r = 1.0f / sum;

    float o[32];
    #pragma unroll
    for (int d = 0; d < 32; d++) o[d] = 0.f;
    #pragma unroll 4
    for (int m = 0; m < 64; m++) {
        float p = s[m] * r;
        #pragma unroll
        for (int d = 0; d < 32; d++) o[d] += p * sv[m][d];
    }
    size_t ob = (size_t)(g * NTOK + n) * CC + h * HD;
    #pragma unroll
    for (int d = 0; d < 32; d++) split_bf16(o[d], g_ao_h[ob + d], g_ao_l[ob + d]);
}

// ---------------- launch ----------------
extern "C" void kernel_launch(void* const* d_in, const int* in_sizes, int n_in,
                              void* d_out, int out_size)
{
    const float* x          = (const float*)d_in[0];
    const float* g1         = (const float*)d_in[1];
    const float* b1         = (const float*)d_in[2];
    const float* Wqkv       = (const float*)d_in[3];
    const float* bqkv       = (const float*)d_in[4];
    const float* bias_table = (const float*)d_in[5];
    const float* Wp         = (const float*)d_in[6];
    const float* bp         = (const float*)d_in[7];
    const float* g2         = (const float*)d_in[8];
    const float* b2         = (const float*)d_in[9];
    const float* W1         = (const float*)d_in[10];
    const float* bb1        = (const float*)d_in[11];
    const float* W2         = (const float*)d_in[12];
    const float* bb2        = (const float*)d_in[13];
    float* out = (float*)d_out;

    const int SMEM = 2 * STG_SZ;
    cudaFuncSetAttribute(tgemm<0, 3*CC, CC>,  cudaFuncAttributeMaxDynamicSharedMemorySize, SMEM);
    cudaFuncSetAttribute(tgemm<1, CC, CC>,    cudaFuncAttributeMaxDynamicSharedMemorySize, SMEM);
    cudaFuncSetAttribute(tgemm<2, HMLP, CC>,  cudaFuncAttributeMaxDynamicSharedMemorySize, SMEM);
    cudaFuncSetAttribute(tgemm<3, CC, HMLP>,  cudaFuncAttributeMaxDynamicSharedMemorySize, SMEM);

    __nv_bfloat16 *wqh, *wql, *wph, *wpl, *w1h, *w1l, *w2h, *w2l;
    cudaGetSymbolAddress((void**)&wqh, g_wqkv_h); cudaGetSymbolAddress((void**)&wql, g_wqkv_l);
    cudaGetSymbolAddress((void**)&wph, g_wp_h);   cudaGetSymbolAddress((void**)&wpl, g_wp_l);
    cudaGetSymbolAddress((void**)&w1h, g_w1_h);   cudaGetSymbolAddress((void**)&w1l, g_w1_l);
    cudaGetSymbolAddress((void**)&w2h, g_w2_h);   cudaGetSymbolAddress((void**)&w2l, g_w2_l);

    cvt_kernel<<<(3*CC*CC + 255) / 256, 256>>>(Wqkv, wqh, wql, 3*CC*CC);
    cvt_kernel<<<(CC*CC   + 255) / 256, 256>>>(Wp,   wph, wpl, CC*CC);
    cvt_kernel<<<(HMLP*CC + 255) / 256, 256>>>(W1,   w1h, w1l, HMLP*CC);
    cvt_kernel<<<(CC*HMLP + 255) / 256, 256>>>(W2,   w2h, w2l, CC*HMLP);

    ln_kernel<0><<<TOK, 128>>>(x, g1, b1);
    tgemm<0, 3*CC, CC><<<dim3(3*CC/128, TOK/128), 256, SMEM>>>(bqkv, nullptr, nullptr);
    attn_kernel<<<dim3(NWIN, NHEAD), 64>>>(bias_table);
    tgemm<1, CC, CC><<<dim3(CC/128, TOK/128), 256, SMEM>>>(bp, nullptr, x);
    ln_kernel<1><<<TOK, 128>>>(nullptr, g2, b2);
    tgemm<2, HMLP, CC><<<dim3(HMLP/128, TOK/128), 256, SMEM>>>(bb1, nullptr, nullptr);
    tgemm<3, CC, HMLP><<<dim3(CC/128, TOK/128), 256, SMEM>>>(bb2, out, nullptr);
}

// round 4
// speedup vs baseline: 2.2600x; 1.0989x over previous
#include <cuda_runtime.h>
#include <cuda_bf16.h>
#include <cstdint>

// ---------------- problem constants ----------------
#define CC 384
#define NHEAD 12
#define HD 32
#define NTOK 64
#define NWIN 1024
#define TOK 65536
#define HMLP 1536
#define QSCALE 0.17677669529663687f   // 32^-0.5

// ---------------- scratch (device globals; no allocations) ----------------
__device__ __nv_bfloat16 g_xw_h [TOK * CC],  g_xw_l [TOK * CC];
__device__ __nv_bfloat16 g_ao_h [TOK * CC],  g_ao_l [TOK * CC];
__device__ __nv_bfloat16 g_ln2_h[TOK * CC],  g_ln2_l[TOK * CC];
__device__ __nv_bfloat16 g_mlp_h[TOK * HMLP],g_mlp_l[TOK * HMLP];
__device__ __nv_bfloat16 g_wqkv_h[3*CC*CC],  g_wqkv_l[3*CC*CC];
__device__ __nv_bfloat16 g_wp_h [CC*CC],     g_wp_l [CC*CC];
__device__ __nv_bfloat16 g_w1_h [HMLP*CC],   g_w1_l [HMLP*CC];
__device__ __nv_bfloat16 g_w2_h [CC*HMLP],   g_w2_l [CC*HMLP];
__device__ float g_q [TOK * CC];
__device__ float g_k [TOK * CC];
__device__ float g_v [TOK * CC];
__device__ float g_x2[TOK * CC];

// ---------------- helpers ----------------
__device__ __forceinline__ uint32_t smem_u32(const void* p) {
    uint32_t a;
    asm("{ .reg .u64 t; cvta.to.shared.u64 t, %1; cvt.u32.u64 %0, t; }" : "=r"(a) : "l"(p));
    return a;
}
__device__ __forceinline__ void cp16(uint32_t saddr, const void* gaddr) {
    asm volatile("cp.async.cg.shared.global [%0], [%1], 16;" :: "r"(saddr), "l"(gaddr));
}
__device__ __forceinline__ void ldm4(uint32_t* r, uint32_t addr) {
    asm volatile("ldmatrix.sync.aligned.m8n8.x4.shared.b16 {%0,%1,%2,%3}, [%4];"
                 : "=r"(r[0]), "=r"(r[1]), "=r"(r[2]), "=r"(r[3]) : "r"(addr));
}
__device__ __forceinline__ void mma16816(float* c, const uint32_t* a, const uint32_t* b) {
    asm volatile("mma.sync.aligned.m16n8k16.row.col.f32.bf16.bf16.f32 "
                 "{%0,%1,%2,%3}, {%4,%5,%6,%7}, {%8,%9}, {%0,%1,%2,%3};"
                 : "+f"(c[0]), "+f"(c[1]), "+f"(c[2]), "+f"(c[3])
                 : "r"(a[0]), "r"(a[1]), "r"(a[2]), "r"(a[3]), "r"(b[0]), "r"(b[1]));
}
__device__ __forceinline__ void split_bf16(float v, __nv_bfloat16& h, __nv_bfloat16& l) {
    h = __float2bfloat16(v);
    l = __float2bfloat16(v - __bfloat162float(h));
}

// ---------------- fused weight fp32 -> bf16 hi/lo (all 4 weights) ----------
#define NW0 (3*CC*CC)
#define NW1 (NW0 + CC*CC)
#define NW2 (NW1 + HMLP*CC)
#define NW3 (NW2 + CC*HMLP)
__global__ __launch_bounds__(256) void cvt_all(const float* __restrict__ wqkv,
                                               const float* __restrict__ wp,
                                               const float* __restrict__ w1,
                                               const float* __restrict__ w2) {
    int i = blockIdx.x * 256 + threadIdx.x;
    if (i >= NW3) return;
    const float* src; __nv_bfloat16 *dh, *dl; int o;
    if (i < NW0)      { src = wqkv; dh = g_wqkv_h; dl = g_wqkv_l; o = i; }
    else if (i < NW1) { src = wp;   dh = g_wp_h;   dl = g_wp_l;   o = i - NW0; }
    else if (i < NW2) { src = w1;   dh = g_w1_h;   dl = g_w1_l;   o = i - NW1; }
    else              { src = w2;   dh = g_w2_h;   dl = g_w2_l;   o = i - NW2; }
    split_bf16(src[o], dh[o], dl[o]);
}

// ---------------- LayerNorm ----------------
template<int MODE>
__global__ __launch_bounds__(128) void ln_kernel(const float* __restrict__ xin,
                                                 const float* __restrict__ gamma,
                                                 const float* __restrict__ beta)
{
    int t = blockIdx.x;
    const float* src;
    __nv_bfloat16 *dh, *dl;
    if constexpr (MODE == 0) {
        int g = t >> 6, n = t & 63;
        int b = g >> 9, wd = (g >> 6) & 7, wh = (g >> 3) & 7, ww = g & 7;
        int i = n >> 4, j = (n >> 2) & 3, k = n & 3;
        int d0 = (wd * 4 + i + 2) & 31;
        int h0 = (wh * 4 + j + 2) & 31;
        int w0 = (ww * 4 + k + 2) & 31;
        src = xin + (size_t)(((b * 32 + d0) * 32 + h0) * 32 + w0) * CC;
        dh = g_xw_h + (size_t)t * CC; dl = g_xw_l + (size_t)t * CC;
    } else {
        src = g_x2 + (size_t)t * CC;
        dh = g_ln2_h + (size_t)t * CC; dl = g_ln2_l + (size_t)t * CC;
    }
    int tid = threadIdx.x;
    float v0 = src[tid], v1 = src[tid + 128], v2 = src[tid + 256];
    float s = v0 + v1 + v2;
    float ss = v0 * v0 + v1 * v1 + v2 * v2;
    #pragma unroll
    for (int o = 16; o > 0; o >>= 1) {
        s  += __shfl_xor_sync(0xffffffffu, s, o);
        ss += __shfl_xor_sync(0xffffffffu, ss, o);
    }
    __shared__ float red[8];
    if ((tid & 31) == 0) { red[tid >> 5] = s; red[4 + (tid >> 5)] = ss; }
    __syncthreads();
    s  = red[0] + red[1] + red[2] + red[3];
    ss = red[4] + red[5] + red[6] + red[7];
    float mu  = s * (1.0f / CC);
    float var = ss * (1.0f / CC) - mu * mu;
    float inv = rsqrtf(var + 1e-5f);
    float o0 = (v0 - mu) * inv * gamma[tid]       + beta[tid];
    float o1 = (v1 - mu) * inv * gamma[tid + 128] + beta[tid + 128];
    float o2 = (v2 - mu) * inv * gamma[tid + 256] + beta[tid + 256];
    split_bf16(o0, dh[tid],       dl[tid]);
    split_bf16(o1, dh[tid + 128], dl[tid + 128]);
    split_bf16(o2, dh[tid + 256], dl[tid + 256]);
}

// ---------------- mma.sync split-bf16 GEMM: C = A @ Bw^T + bias ------------
// 128x128 CTA tile, BK=32, 3-stage cp.async ring, ONE barrier per chunk.
// 3-term split (Ah*Bh + Ah*Bl + Al*Bh) in 3 independent passes over 16 accs.
#define STG_A_H 0
#define STG_A_L 10240
#define STG_B_H 20480
#define STG_B_L 30720
#define STG_SZ  40960
#define NSTAGE  3

template<int EPI, int N, int K>
__global__ __launch_bounds__(256, 1) void tgemm(const float* __restrict__ bias,
                                                float* __restrict__ Cout,
                                                const float* __restrict__ extra)
{
    const __nv_bfloat16 *Ah, *Al, *Bh, *Bl;
    if constexpr (EPI == 0)      { Ah = g_xw_h;  Al = g_xw_l;  Bh = g_wqkv_h; Bl = g_wqkv_l; }
    else if constexpr (EPI == 1) { Ah = g_ao_h;  Al = g_ao_l;  Bh = g_wp_h;   Bl = g_wp_l;   }
    else if constexpr (EPI == 2) { Ah = g_ln2_h; Al = g_ln2_l; Bh = g_w1_h;   Bl = g_w1_l;   }
    else                         { Ah = g_mlp_h; Al = g_mlp_l; Bh = g_w2_h;   Bl = g_w2_l;   }

    extern __shared__ char smem[];
    const uint32_t sb = smem_u32(smem);
    const int tid = threadIdx.x;
    const int wid = tid >> 5, lane = tid & 31;
    const int wm = wid & 1, wn = wid >> 1;
    const int m0 = blockIdx.y * 128, n0 = blockIdx.x * 128;
    constexpr int NC = K / 32;

    auto issue = [&](int c, int st) {
        int k0 = c * 32;
        uint32_t base = sb + (uint32_t)st * STG_SZ;
        #pragma unroll
        for (int t = 0; t < 2; t++) {
            int e = tid + t * 256;
            int r = e >> 2, cv = e & 3;
            uint32_t so = (uint32_t)(r * 80 + cv * 16);
            size_t ga = (size_t)(m0 + r) * K + k0 + cv * 8;
            size_t gb = (size_t)(n0 + r) * K + k0 + cv * 8;
            cp16(base + STG_A_H + so, Ah + ga);
            cp16(base + STG_A_L + so, Al + ga);
            cp16(base + STG_B_H + so, Bh + gb);
            cp16(base + STG_B_L + so, Bl + gb);
        }
        asm volatile("cp.async.commit_group;");
    };

    const int lr = lane & 7;
    const int aRow = wm * 64 + lr + ((lane >> 3) & 1) * 8;
    const int aK   = (lane >> 4) * 8;
    const int bRow = wn * 32 + lr + (lane >> 4) * 8;
    const int bK   = ((lane >> 3) & 1) * 8;

    float acc[4][4][4];
    #pragma unroll
    for (int a = 0; a < 4; a++)
        #pragma unroll
        for (int b = 0; b < 4; b++)
            #pragma unroll
            for (int c = 0; c < 4; c++) acc[a][b][c] = 0.f;

    issue(0, 0);
    issue(1, 1);

    for (int c = 0; c < NC; c++) {
        if (c == NC - 1) asm volatile("cp.async.wait_group 0;");
        else             asm volatile("cp.async.wait_group 1;");
        __syncthreads();
        if (c + 2 < NC) issue(c + 2, (c + 2) % NSTAGE);

        uint32_t base = sb + (uint32_t)(c % NSTAGE) * STG_SZ;
        #pragma unroll
        for (int ks = 0; ks < 2; ks++) {
            uint32_t a_h[4][4], a_l[4][4];
            #pragma unroll
            for (int mt = 0; mt < 4; mt++) {
                uint32_t off = (uint32_t)((aRow + mt * 16) * 40 + ks * 16 + aK) * 2;
                ldm4(a_h[mt], base + STG_A_H + off);
                ldm4(a_l[mt], base + STG_A_L + off);
            }
            uint32_t b_h[4][2], b_l[4][2];
            #pragma unroll
            for (int p = 0; p < 2; p++) {
                uint32_t off = (uint32_t)((bRow + p * 16) * 40 + ks * 16 + bK) * 2;
                uint32_t r4[4];
                ldm4(r4, base + STG_B_H + off);
                b_h[2*p][0] = r4[0]; b_h[2*p][1] = r4[1];
                b_h[2*p+1][0] = r4[2]; b_h[2*p+1][1] = r4[3];
                ldm4(r4, base + STG_B_L + off);
                b_l[2*p][0] = r4[0]; b_l[2*p][1] = r4[1];
                b_l[2*p+1][0] = r4[2]; b_l[2*p+1][1] = r4[3];
            }
            // pass 1: hi*hi (16 independent accumulators)
            #pragma unroll
            for (int mt = 0; mt < 4; mt++)
                #pragma unroll
                for (int nt = 0; nt < 4; nt++) mma16816(acc[mt][nt], a_h[mt], b_h[nt]);
            // pass 2: hi*lo
            #pragma unroll
            for (int mt = 0; mt < 4; mt++)
                #pragma unroll
                for (int nt = 0; nt < 4; nt++) mma16816(acc[mt][nt], a_h[mt], b_l[nt]);
            // pass 3: lo*hi
            #pragma unroll
            for (int mt = 0; mt < 4; mt++)
                #pragma unroll
                for (int nt = 0; nt < 4; nt++) mma16816(acc[mt][nt], a_l[mt], b_h[nt]);
        }
    }

    // ---------------- epilogue ----------------
    const int mrow0 = m0 + wm * 64 + (lane >> 2);
    const int ncol0 = n0 + wn * 32 + (lane & 3) * 2;

    #pragma unroll
    for (int mt = 0; mt < 4; mt++) {
        #pragma unroll
        for (int nt = 0; nt < 4; nt++) {
            #pragma unroll
            for (int half = 0; half < 2; half++) {
                int row = mrow0 + mt * 16 + half * 8;
                int col = ncol0 + nt * 8;
                float v0 = acc[mt][nt][half * 2]     + bias[col];
                float v1 = acc[mt][nt][half * 2 + 1] + bias[col + 1];

                if constexpr (EPI == 0) {
                    int s = col / CC; int rr = col - s * CC;
                    int hh = rr >> 5, d = rr & 31;
                    float* dst = (s == 0) ? g_q : (s == 1) ? g_k : g_v;
                    if (s == 0) { v0 *= QSCALE; v1 *= QSCALE; }
                    size_t o = (((size_t)(row >> 6) * NHEAD + hh) * NTOK + (row & 63)) * HD + d;
                    *(float2*)(dst + o) = make_float2(v0, v1);
                } else if constexpr (EPI == 1) {
                    int g = row >> 6, nn = row & 63;
                    int b = g >> 9, wd = (g >> 6) & 7, wh = (g >> 3) & 7, ww = g & 7;
                    int i3 = nn >> 4, j3 = (nn >> 2) & 3, k3 = nn & 3;
                    int d0 = (wd * 4 + i3 + 2) & 31;
                    int h0 = (wh * 4 + j3 + 2) & 31;
                    int w0 = (ww * 4 + k3 + 2) & 31;
                    size_t nat = (size_t)(((b * 32 + d0) * 32 + h0) * 32 + w0) * CC + col;
                    float2 e = *(const float2*)(extra + nat);
                    *(float2*)(g_x2 + nat) = make_float2(v0 + e.x, v1 + e.y);
                } else if constexpr (EPI == 2) {
                    size_t o = (size_t)row * HMLP + col;
                    float t0 = v0 * 0.5f * (1.0f + erff(v0 * 0.70710678118654752f));
                    float t1 = v1 * 0.5f * (1.0f + erff(v1 * 0.70710678118654752f));
                    __nv_bfloat16 h0b, l0b, h1b, l1b;
                    split_bf16(t0, h0b, l0b);
                    split_bf16(t1, h1b, l1b);
                    *(__nv_bfloat162*)(g_mlp_h + o) = __nv_bfloat162(h0b, h1b);
                    *(__nv_bfloat162*)(g_mlp_l + o) = __nv_bfloat162(l0b, l1b);
                } else {
                    size_t o = (size_t)row * CC + col;
                    float2 e = *(const float2*)(g_x2 + o);
                    *(float2*)(Cout + o) = make_float2(v0 + e.x, v1 + e.y);
                }
            }
        }
    }
}

// ---------------- windowed attention: one block per (window, head) ---------
// q from global into registers; k/v in smem, broadcast float4 reads.
__global__ __launch_bounds__(64) void attn_kernel(const float* __restrict__ bias_table)
{
    int g = blockIdx.x, h = blockIdx.y;
    __shared__ float sk[64][32];
    __shared__ float sv[64][32];
    __shared__ float sbias[343];

    int tid = threadIdx.x;
    const float* qb = g_q + (size_t)(g * NHEAD + h) * NTOK * HD;
    const float* kb = g_k + (size_t)(g * NHEAD + h) * NTOK * HD;
    const float* vb = g_v + (size_t)(g * NHEAD + h) * NTOK * HD;
    #pragma unroll
    for (int e = tid * 4; e < NTOK * HD; e += 256) {
        *(float4*)(&sk[0][0] + e) = *(const float4*)(kb + e);
        *(float4*)(&sv[0][0] + e) = *(const float4*)(vb + e);
    }
    for (int idx = tid; idx < 343; idx += 64) sbias[idx] = bias_table[idx * NHEAD + h];

    int n = tid;
    float qv[32];
    #pragma unroll
    for (int d4 = 0; d4 < 8; d4++) {
        float4 q4 = *(const float4*)(qb + n * HD + d4 * 4);
        qv[d4*4] = q4.x; qv[d4*4+1] = q4.y; qv[d4*4+2] = q4.z; qv[d4*4+3] = q4.w;
    }
    __syncthreads();

    int i = n >> 4, j = (n >> 2) & 3, kk = n & 3;
    int wd = (g >> 6) & 7, wh = (g >> 3) & 7, ww = g & 7;
    int rd = (wd < 7) ? 0 : ((i  < 2) ? 1 : 2);
    int rh = (wh < 7) ? 0 : ((j  < 2) ? 1 : 2);
    int rw = (ww < 7) ? 0 : ((kk < 2) ? 1 : 2);
    int cn = rd * 9 + rh * 3 + rw;

    float s[64];
    float mx = -1e30f;
    #pragma unroll 4
    for (int m = 0; m < 64; m++) {
        float acc = 0.f;
        #pragma unroll
        for (int d4 = 0; d4 < 8; d4++) {
            float4 k4 = *(const float4*)(&sk[m][d4 * 4]);
            acc += qv[d4*4] * k4.x + qv[d4*4+1] * k4.y + qv[d4*4+2] * k4.z + qv[d4*4+3] * k4.w;
        }
        int i2 = m >> 4, j2 = (m >> 2) & 3, k2 = m & 3;
        int idx = (i - i2 + 3) * 49 + (j - j2 + 3) * 7 + (kk - k2 + 3);
        acc += sbias[idx];
        int cm = ((wd < 7) ? 0 : ((i2 < 2) ? 1 : 2)) * 9
               + ((wh < 7) ? 0 : ((j2 < 2) ? 1 : 2)) * 3
               + ((ww < 7) ? 0 : ((k2 < 2) ? 1 : 2));
        if (cm != cn) acc -= 100.0f;
        s[m] = acc;
        mx = fmaxf(mx, acc);
    }
    float sum = 0.f;
    #pragma unroll
    for (int m = 0; m < 64; m++) { s[m] = __expf(s[m] - mx); sum += s[m]; }
    float r = 1.0f / sum;

    float o[32];
    #pragma unroll
    for (int d = 0; d < 32; d++) o[d] = 0.f;
    #pragma unroll 4
    for (int m = 0; m < 64; m++) {
        float p = s[m] * r;
        #pragma unroll
        for (int d4 = 0; d4 < 8; d4++) {
            float4 v4 = *(const float4*)(&sv[m][d4 * 4]);
            o[d4*4]   += p * v4.x; o[d4*4+1] += p * v4.y;
            o[d4*4+2] += p * v4.z; o[d4*4+3] += p * v4.w;
        }
    }
    size_t ob = (size_t)(g * NTOK + n) * CC + h * HD;
    #pragma unroll
    for (int d = 0; d < 32; d += 2) {
        __nv_bfloat16 h0, l0, h1, l1;
        split_bf16(o[d],     h0, l0);
        split_bf16(o[d + 1], h1, l1);
        *(__nv_bfloat162*)(g_ao_h + ob + d) = __nv_bfloat162(h0, h1);
        *(__nv_bfloat162*)(g_ao_l + ob + d) = __nv_bfloat162(l0, l1);
    }
}

// ---------------- launch ----------------
extern "C" void kernel_launch(void* const* d_in, const int* in_sizes, int n_in,
                              void* d_out, int out_size)
{
    const float* x          = (const float*)d_in[0];
    const float* g1         = (const float*)d_in[1];
    const float* b1         = (const float*)d_in[2];
    const float* Wqkv       = (const float*)d_in[3];
    const float* bqkv       = (const float*)d_in[4];
    const float* bias_table = (const float*)d_in[5];
    const float* Wp         = (const float*)d_in[6];
    const float* bp         = (const float*)d_in[7];
    const float* g2         = (const float*)d_in[8];
    const float* b2         = (const float*)d_in[9];
    const float* W1         = (const float*)d_in[10];
    const float* bb1        = (const float*)d_in[11];
    const float* W2         = (const float*)d_in[12];
    const float* bb2        = (const float*)d_in[13];
    float* out = (float*)d_out;

    const int SMEM = NSTAGE * STG_SZ;
    cudaFuncSetAttribute(tgemm<0, 3*CC, CC>,  cudaFuncAttributeMaxDynamicSharedMemorySize, SMEM);
    cudaFuncSetAttribute(tgemm<1, CC, CC>,    cudaFuncAttributeMaxDynamicSharedMemorySize, SMEM);
    cudaFuncSetAttribute(tgemm<2, HMLP, CC>,  cudaFuncAttributeMaxDynamicSharedMemorySize, SMEM);
    cudaFuncSetAttribute(tgemm<3, CC, HMLP>,  cudaFuncAttributeMaxDynamicSharedMemorySize, SMEM);

    cvt_all<<<(NW3 + 255) / 256, 256>>>(Wqkv, Wp, W1, W2);
    ln_kernel<0><<<TOK, 128>>>(x, g1, b1);
    tgemm<0, 3*CC, CC><<<dim3(3*CC/128, TOK/128), 256, SMEM>>>(bqkv, nullptr, nullptr);
    attn_kernel<<<dim3(NWIN, NHEAD), 64>>>(bias_table);
    tgemm<1, CC, CC><<<dim3(CC/128, TOK/128), 256, SMEM>>>(bp, nullptr, x);
    ln_kernel<1><<<TOK, 128>>>(nullptr, g2, b2);
    tgemm<2, HMLP, CC><<<dim3(HMLP/128, TOK/128), 256, SMEM>>>(bb1, nullptr, nullptr);
    tgemm<3, CC, HMLP><<<dim3(CC/128, TOK/128), 256, SMEM>>>(bb2, out, nullptr);
}

// round 5
// speedup vs baseline: 2.9830x; 1.3199x over previous
#include <cuda_runtime.h>
#include <cuda_fp16.h>
#include <cuda_bf16.h>
#include <cstdint>

// ---------------- problem constants ----------------
#define CC 384
#define NHEAD 12
#define HD 32
#define NTOK 64
#define NWIN 1024
#define TOK 65536
#define HMLP 1536
#define QSCALE 0.17677669529663687f   // 32^-0.5

// ---------------- scratch (device globals; no allocations) ----------------
__device__ __half g_xw [TOK * CC];      // activations: single fp16
__device__ __half g_ao [TOK * CC];
__device__ __half g_ln2[TOK * CC];
__device__ __half g_mlp[TOK * HMLP];
__device__ __half g_wqkv_h[3*CC*CC], g_wqkv_l[3*CC*CC];   // weights: fp16 hi/lo
__device__ __half g_wp_h [CC*CC],    g_wp_l [CC*CC];
__device__ __half g_w1_h [HMLP*CC],  g_w1_l [HMLP*CC];
__device__ __half g_w2_h [CC*HMLP],  g_w2_l [CC*HMLP];
__device__ float g_q [TOK * CC];
__device__ float g_k [TOK * CC];
__device__ float g_v [TOK * CC];
__device__ float g_x2[TOK * CC];

// ---------------- helpers ----------------
__device__ __forceinline__ uint32_t smem_u32(const void* p) {
    uint32_t a;
    asm("{ .reg .u64 t; cvta.to.shared.u64 t, %1; cvt.u32.u64 %0, t; }" : "=r"(a) : "l"(p));
    return a;
}
__device__ __forceinline__ void cp16(uint32_t saddr, const void* gaddr) {
    asm volatile("cp.async.cg.shared.global [%0], [%1], 16;" :: "r"(saddr), "l"(gaddr));
}
__device__ __forceinline__ void ldm4(uint32_t* r, uint32_t addr) {
    asm volatile("ldmatrix.sync.aligned.m8n8.x4.shared.b16 {%0,%1,%2,%3}, [%4];"
                 : "=r"(r[0]), "=r"(r[1]), "=r"(r[2]), "=r"(r[3]) : "r"(addr));
}
__device__ __forceinline__ void mma16816(float* c, const uint32_t* a, const uint32_t* b) {
    asm volatile("mma.sync.aligned.m16n8k16.row.col.f32.f16.f16.f32 "
                 "{%0,%1,%2,%3}, {%4,%5,%6,%7}, {%8,%9}, {%0,%1,%2,%3};"
                 : "+f"(c[0]), "+f"(c[1]), "+f"(c[2]), "+f"(c[3])
                 : "r"(a[0]), "r"(a[1]), "r"(a[2]), "r"(a[3]), "r"(b[0]), "r"(b[1]));
}
__device__ __forceinline__ void split_h(float v, __half& h, __half& l) {
    h = __float2half_rn(v);
    l = __float2half_rn(v - __half2float(h));
}

// ---------------- fused weight fp32 -> fp16 hi/lo ----------
#define NW0 (3*CC*CC)
#define NW1 (NW0 + CC*CC)
#define NW2 (NW1 + HMLP*CC)
#define NW3 (NW2 + CC*HMLP)
__global__ __launch_bounds__(256) void cvt_all(const float* __restrict__ wqkv,
                                               const float* __restrict__ wp,
                                               const float* __restrict__ w1,
                                               const float* __restrict__ w2) {
    int i = blockIdx.x * 256 + threadIdx.x;
    if (i >= NW3) return;
    const float* src; __half *dh, *dl; int o;
    if (i < NW0)      { src = wqkv; dh = g_wqkv_h; dl = g_wqkv_l; o = i; }
    else if (i < NW1) { src = wp;   dh = g_wp_h;   dl = g_wp_l;   o = i - NW0; }
    else if (i < NW2) { src = w1;   dh = g_w1_h;   dl = g_w1_l;   o = i - NW1; }
    else              { src = w2;   dh = g_w2_h;   dl = g_w2_l;   o = i - NW2; }
    split_h(src[o], dh[o], dl[o]);
}

// ---------------- LayerNorm ----------------
template<int MODE>
__global__ __launch_bounds__(128) void ln_kernel(const float* __restrict__ xin,
                                                 const float* __restrict__ gamma,
                                                 const float* __restrict__ beta)
{
    int t = blockIdx.x;
    const float* src;
    __half* dh;
    if constexpr (MODE == 0) {
        int g = t >> 6, n = t & 63;
        int b = g >> 9, wd = (g >> 6) & 7, wh = (g >> 3) & 7, ww = g & 7;
        int i = n >> 4, j = (n >> 2) & 3, k = n & 3;
        int d0 = (wd * 4 + i + 2) & 31;
        int h0 = (wh * 4 + j + 2) & 31;
        int w0 = (ww * 4 + k + 2) & 31;
        src = xin + (size_t)(((b * 32 + d0) * 32 + h0) * 32 + w0) * CC;
        dh = g_xw + (size_t)t * CC;
    } else {
        src = g_x2 + (size_t)t * CC;
        dh = g_ln2 + (size_t)t * CC;
    }
    int tid = threadIdx.x;
    float v0 = src[tid], v1 = src[tid + 128], v2 = src[tid + 256];
    float s = v0 + v1 + v2;
    float ss = v0 * v0 + v1 * v1 + v2 * v2;
    #pragma unroll
    for (int o = 16; o > 0; o >>= 1) {
        s  += __shfl_xor_sync(0xffffffffu, s, o);
        ss += __shfl_xor_sync(0xffffffffu, ss, o);
    }
    __shared__ float red[8];
    if ((tid & 31) == 0) { red[tid >> 5] = s; red[4 + (tid >> 5)] = ss; }
    __syncthreads();
    s  = red[0] + red[1] + red[2] + red[3];
    ss = red[4] + red[5] + red[6] + red[7];
    float mu  = s * (1.0f / CC);
    float var = ss * (1.0f / CC) - mu * mu;
    float inv = rsqrtf(var + 1e-5f);
    dh[tid]       = __float2half_rn((v0 - mu) * inv * gamma[tid]       + beta[tid]);
    dh[tid + 128] = __float2half_rn((v1 - mu) * inv * gamma[tid + 128] + beta[tid + 128]);
    dh[tid + 256] = __float2half_rn((v2 - mu) * inv * gamma[tid + 256] + beta[tid + 256]);
}

// ---------------- mma.sync fp16 2-term GEMM: C = A @ (Bh+Bl)^T + bias ------
// 128x128 CTA tile, BK=32, 3-stage cp.async ring, one barrier per chunk.
#define STG_A   0
#define STG_B_H 10240
#define STG_B_L 20480
#define STG_SZ  30720
#define NSTAGE  3

template<int EPI, int N, int K>
__global__ __launch_bounds__(256, 1) void tgemm(const float* __restrict__ bias,
                                                float* __restrict__ Cout,
                                                const float* __restrict__ extra)
{
    const __half *A, *Bh, *Bl;
    if constexpr (EPI == 0)      { A = g_xw;  Bh = g_wqkv_h; Bl = g_wqkv_l; }
    else if constexpr (EPI == 1) { A = g_ao;  Bh = g_wp_h;   Bl = g_wp_l;   }
    else if constexpr (EPI == 2) { A = g_ln2; Bh = g_w1_h;   Bl = g_w1_l;   }
    else                         { A = g_mlp; Bh = g_w2_h;   Bl = g_w2_l;   }

    extern __shared__ char smem[];
    const uint32_t sb = smem_u32(smem);
    const int tid = threadIdx.x;
    const int wid = tid >> 5, lane = tid & 31;
    const int wm = wid & 1, wn = wid >> 1;
    const int m0 = blockIdx.y * 128, n0 = blockIdx.x * 128;
    constexpr int NC = K / 32;

    auto issue = [&](int c, int st) {
        int k0 = c * 32;
        uint32_t base = sb + (uint32_t)st * STG_SZ;
        #pragma unroll
        for (int t = 0; t < 2; t++) {
            int e = tid + t * 256;
            int r = e >> 2, cv = e & 3;
            uint32_t so = (uint32_t)(r * 80 + cv * 16);
            size_t ga = (size_t)(m0 + r) * K + k0 + cv * 8;
            size_t gb = (size_t)(n0 + r) * K + k0 + cv * 8;
            cp16(base + STG_A   + so, A  + ga);
            cp16(base + STG_B_H + so, Bh + gb);
            cp16(base + STG_B_L + so, Bl + gb);
        }
        asm volatile("cp.async.commit_group;");
    };

    const int lr = lane & 7;
    const int aRow = wm * 64 + lr + ((lane >> 3) & 1) * 8;
    const int aK   = (lane >> 4) * 8;
    const int bRow = wn * 32 + lr + (lane >> 4) * 8;
    const int bK   = ((lane >> 3) & 1) * 8;

    float acc[4][4][4];
    #pragma unroll
    for (int a = 0; a < 4; a++)
        #pragma unroll
        for (int b = 0; b < 4; b++)
            #pragma unroll
            for (int c = 0; c < 4; c++) acc[a][b][c] = 0.f;

    issue(0, 0);
    issue(1, 1);

    for (int c = 0; c < NC; c++) {
        if (c == NC - 1) asm volatile("cp.async.wait_group 0;");
        else             asm volatile("cp.async.wait_group 1;");
        __syncthreads();
        if (c + 2 < NC) issue(c + 2, (c + 2) % NSTAGE);

        uint32_t base = sb + (uint32_t)(c % NSTAGE) * STG_SZ;
        #pragma unroll
        for (int ks = 0; ks < 2; ks++) {
            uint32_t a_r[4][4];
            #pragma unroll
            for (int mt = 0; mt < 4; mt++) {
                uint32_t off = (uint32_t)((aRow + mt * 16) * 40 + ks * 16 + aK) * 2;
                ldm4(a_r[mt], base + STG_A + off);
            }
            uint32_t b_h[4][2], b_l[4][2];
            #pragma unroll
            for (int p = 0; p < 2; p++) {
                uint32_t off = (uint32_t)((bRow + p * 16) * 40 + ks * 16 + bK) * 2;
                uint32_t r4[4];
                ldm4(r4, base + STG_B_H + off);
                b_h[2*p][0] = r4[0]; b_h[2*p][1] = r4[1];
                b_h[2*p+1][0] = r4[2]; b_h[2*p+1][1] = r4[3];
                ldm4(r4, base + STG_B_L + off);
                b_l[2*p][0] = r4[0]; b_l[2*p][1] = r4[1];
                b_l[2*p+1][0] = r4[2]; b_l[2*p+1][1] = r4[3];
            }
            // pass 1: A * Bh (16 independent accumulators)
            #pragma unroll
            for (int mt = 0; mt < 4; mt++)
                #pragma unroll
                for (int nt = 0; nt < 4; nt++) mma16816(acc[mt][nt], a_r[mt], b_h[nt]);
            // pass 2: A * Bl
            #pragma unroll
            for (int mt = 0; mt < 4; mt++)
                #pragma unroll
                for (int nt = 0; nt < 4; nt++) mma16816(acc[mt][nt], a_r[mt], b_l[nt]);
        }
    }

    // ---------------- epilogue ----------------
    const int mrow0 = m0 + wm * 64 + (lane >> 2);
    const int ncol0 = n0 + wn * 32 + (lane & 3) * 2;

    #pragma unroll
    for (int mt = 0; mt < 4; mt++) {
        #pragma unroll
        for (int nt = 0; nt < 4; nt++) {
            #pragma unroll
            for (int half = 0; half < 2; half++) {
                int row = mrow0 + mt * 16 + half * 8;
                int col = ncol0 + nt * 8;
                float v0 = acc[mt][nt][half * 2]     + bias[col];
                float v1 = acc[mt][nt][half * 2 + 1] + bias[col + 1];

                if constexpr (EPI == 0) {
                    int s = col / CC; int rr = col - s * CC;
                    int hh = rr >> 5, d = rr & 31;
                    float* dst = (s == 0) ? g_q : (s == 1) ? g_k : g_v;
                    if (s == 0) { v0 *= QSCALE; v1 *= QSCALE; }
                    size_t o = (((size_t)(row >> 6) * NHEAD + hh) * NTOK + (row & 63)) * HD + d;
                    *(float2*)(dst + o) = make_float2(v0, v1);
                } else if constexpr (EPI == 1) {
                    int g = row >> 6, nn = row & 63;
                    int b = g >> 9, wd = (g >> 6) & 7, wh = (g >> 3) & 7, ww = g & 7;
                    int i3 = nn >> 4, j3 = (nn >> 2) & 3, k3 = nn & 3;
                    int d0 = (wd * 4 + i3 + 2) & 31;
                    int h0 = (wh * 4 + j3 + 2) & 31;
                    int w0 = (ww * 4 + k3 + 2) & 31;
                    size_t nat = (size_t)(((b * 32 + d0) * 32 + h0) * 32 + w0) * CC + col;
                    float2 e = *(const float2*)(extra + nat);
                    *(float2*)(g_x2 + nat) = make_float2(v0 + e.x, v1 + e.y);
                } else if constexpr (EPI == 2) {
                    size_t o = (size_t)row * HMLP + col;
                    float t0 = v0 * 0.5f * (1.0f + erff(v0 * 0.70710678118654752f));
                    float t1 = v1 * 0.5f * (1.0f + erff(v1 * 0.70710678118654752f));
                    *(__half2*)(g_mlp + o) = __half2(__float2half_rn(t0), __float2half_rn(t1));
                } else {
                    size_t o = (size_t)row * CC + col;
                    float2 e = *(const float2*)(g_x2 + o);
                    *(float2*)(Cout + o) = make_float2(v0 + e.x, v1 + e.y);
                }
            }
        }
    }
}

// ---------------- windowed attention: one block per (window, head) ---------
// phase-reused smem buffer: K during QK, then V during PV (scores in regs).
__global__ __launch_bounds__(64) void attn_kernel(const float* __restrict__ bias_table)
{
    int g = blockIdx.x, h = blockIdx.y;
    __shared__ float skv[64][32];
    __shared__ float sbias[343];

    int tid = threadIdx.x;
    const float* qb = g_q + (size_t)(g * NHEAD + h) * NTOK * HD;
    const float* kb = g_k + (size_t)(g * NHEAD + h) * NTOK * HD;
    const float* vb = g_v + (size_t)(g * NHEAD + h) * NTOK * HD;
    #pragma unroll
    for (int e = tid * 4; e < NTOK * HD; e += 256)
        *(float4*)(&skv[0][0] + e) = *(const float4*)(kb + e);
    for (int idx = tid; idx < 343; idx += 64) sbias[idx] = bias_table[idx * NHEAD + h];

    int n = tid;
    float qv[32];
    #pragma unroll
    for (int d4 = 0; d4 < 8; d4++) {
        float4 q4 = *(const float4*)(qb + n * HD + d4 * 4);
        qv[d4*4] = q4.x; qv[d4*4+1] = q4.y; qv[d4*4+2] = q4.z; qv[d4*4+3] = q4.w;
    }
    __syncthreads();

    int i = n >> 4, j = (n >> 2) & 3, kk = n & 3;
    int wd = (g >> 6) & 7, wh = (g >> 3) & 7, ww = g & 7;
    int rd = (wd < 7) ? 0 : ((i  < 2) ? 1 : 2);
    int rh = (wh < 7) ? 0 : ((j  < 2) ? 1 : 2);
    int rw = (ww < 7) ? 0 : ((kk < 2) ? 1 : 2);
    int cn = rd * 9 + rh * 3 + rw;

    float s[64];
    float mx = -1e30f;
    #pragma unroll 4
    for (int m = 0; m < 64; m++) {
        float acc = 0.f;
        #pragma unroll
        for (int d4 = 0; d4 < 8; d4++) {
            float4 k4 = *(const float4*)(&skv[m][d4 * 4]);
            acc += qv[d4*4] * k4.x + qv[d4*4+1] * k4.y + qv[d4*4+2] * k4.z + qv[d4*4+3] * k4.w;
        }
        int i2 = m >> 4, j2 = (m >> 2) & 3, k2 = m & 3;
        int idx = (i - i2 + 3) * 49 + (j - j2 + 3) * 7 + (kk - k2 + 3);
        acc += sbias[idx];
        int cm = ((wd < 7) ? 0 : ((i2 < 2) ? 1 : 2)) * 9
               + ((wh < 7) ? 0 : ((j2 < 2) ? 1 : 2)) * 3
               + ((ww < 7) ? 0 : ((k2 < 2) ? 1 : 2));
        if (cm != cn) acc -= 100.0f;
        s[m] = acc;
        mx = fmaxf(mx, acc);
    }
    float sum = 0.f;
    #pragma unroll
    for (int m = 0; m < 64; m++) { s[m] = __expf(s[m] - mx); sum += s[m]; }
    float r = 1.0f / sum;
    #pragma unroll
    for (int m = 0; m < 64; m++) s[m] *= r;

    // swap buffer to V
    __syncthreads();
    #pragma unroll
    for (int e = tid * 4; e < NTOK * HD; e += 256)
        *(float4*)(&skv[0][0] + e) = *(const float4*)(vb + e);
    __syncthreads();

    float o[32];
    #pragma unroll
    for (int d = 0; d < 32; d++) o[d] = 0.f;
    #pragma unroll 4
    for (int m = 0; m < 64; m++) {
        float p = s[m];
        #pragma unroll
        for (int d4 = 0; d4 < 8; d4++) {
            float4 v4 = *(const float4*)(&skv[m][d4 * 4]);
            o[d4*4]   += p * v4.x; o[d4*4+1] += p * v4.y;
            o[d4*4+2] += p * v4.z; o[d4*4+3] += p * v4.w;
        }
    }
    size_t ob = (size_t)(g * NTOK + n) * CC + h * HD;
    #pragma unroll
    for (int d = 0; d < 32; d += 2)
        *(__half2*)(g_ao + ob + d) = __half2(__float2half_rn(o[d]), __float2half_rn(o[d+1]));
}

// ---------------- launch ----------------
extern "C" void kernel_launch(void* const* d_in, const int* in_sizes, int n_in,
                              void* d_out, int out_size)
{
    const float* x          = (const float*)d_in[0];
    const float* g1         = (const float*)d_in[1];
    const float* b1         = (const float*)d_in[2];
    const float* Wqkv       = (const float*)d_in[3];
    const float* bqkv       = (const float*)d_in[4];
    const float* bias_table = (const float*)d_in[5];
    const float* Wp         = (const float*)d_in[6];
    const float* bp         = (const float*)d_in[7];
    const float* g2         = (const float*)d_in[8];
    const float* b2         = (const float*)d_in[9];
    const float* W1         = (const float*)d_in[10];
    const float* bb1        = (const float*)d_in[11];
    const float* W2         = (const float*)d_in[12];
    const float* bb2        = (const float*)d_in[13];
    float* out = (float*)d_out;

    const int SMEM = NSTAGE * STG_SZ;
    cudaFuncSetAttribute(tgemm<0, 3*CC, CC>,  cudaFuncAttributeMaxDynamicSharedMemorySize, SMEM);
    cudaFuncSetAttribute(tgemm<1, CC, CC>,    cudaFuncAttributeMaxDynamicSharedMemorySize, SMEM);
    cudaFuncSetAttribute(tgemm<2, HMLP, CC>,  cudaFuncAttributeMaxDynamicSharedMemorySize, SMEM);
    cudaFuncSetAttribute(tgemm<3, CC, HMLP>,  cudaFuncAttributeMaxDynamicSharedMemorySize, SMEM);

    cvt_all<<<(NW3 + 255) / 256, 256>>>(Wqkv, Wp, W1, W2);
    ln_kernel<0><<<TOK, 128>>>(x, g1, b1);
    tgemm<0, 3*CC, CC><<<dim3(3*CC/128, TOK/128), 256, SMEM>>>(bqkv, nullptr, nullptr);
    attn_kernel<<<dim3(NWIN, NHEAD), 64>>>(bias_table);
    tgemm<1, CC, CC><<<dim3(CC/128, TOK/128), 256, SMEM>>>(bp, nullptr, x);
    ln_kernel<1><<<TOK, 128>>>(nullptr, g2, b2);
    tgemm<2, HMLP, CC><<<dim3(HMLP/128, TOK/128), 256, SMEM>>>(bb1, nullptr, nullptr);
    tgemm<3, CC, HMLP><<<dim3(CC/128, TOK/128), 256, SMEM>>>(bb2, out, nullptr);
}